// round 17
// baseline (speedup 1.0000x reference)
#include <cuda_runtime.h>

// Problem constants
#define NB 16
#define NC 3
#define H 768
#define W 768
#define HS 48            // H/16
#define WS 48            // W/16
#define NPIX (HS * WS)   // 2304
#define RADIUS 8

// exp(-(50*cd + 0.02*sd)) = exp2( -LOG2E*(50*cd + 0.02*sd) )
#define C_DOT   144.269504089f   // 2*50*log2(e)
#define C_SQ     72.134752044f   // 50*log2(e)
#define C_SP      0.028853901f   // 0.02*log2(e)

__device__ __forceinline__ float ex2(float x) {
    float r;
    asm("ex2.approx.ftz.f32 %0, %1;" : "=f"(r) : "f"(x));
    return r;
}

// 16x bilinear downsample of one cell, inline. Half-pixel centers =>
// src = 16*i + 7.5, exact 0.5/0.5 weights => average of the 2x2 pixel
// block at (16y+7, 16x+7), rows first then columns (matches separable
// jax.image.resize). Returns (f0, f1, f2, |f|^2).
__device__ __forceinline__ float4 feat(const float* __restrict__ img,
                                       int b, int i) {
    const int yi = i / WS;
    const int xi = i - yi * WS;
    const int y0 = yi * 16 + 7;
    const int x0 = xi * 16 + 7;          // odd offset -> scalar loads

    float f[3];
#pragma unroll
    for (int c = 0; c < 3; ++c) {
        const float* p = img + ((size_t)(b * NC + c) * H + y0) * W + x0;
        float r0 = 0.5f * (__ldg(p)     + __ldg(p + 1));
        float r1 = 0.5f * (__ldg(p + W) + __ldg(p + W + 1));
        f[c] = 0.5f * (r0 + r1);
    }
    return make_float4(f[0], f[1], f[2],
                       f[0] * f[0] + f[1] * f[1] + f[2] * f[2]);
}

// ---------------------------------------------------------------------------
// Single-kernel affinity: R14 store structure, barrier-free inline features.
// Grid (144, 16): block bx handles rows i = bx + it*144, it = 0..15.
// Stride 144 == 3*WS => xi constant per block.
// Phase 1: out-of-band-dy rows -> zero STG.128s. Predicate is pure dy
//   (warp-coherent: consecutive q share yj) — R15 showed per-lane dx
//   predicates here fragment the store wavefronts; never mix them in.
// Phase 2: in-band rows. ALL threads store (warp-uniform), but only the
//   ~5 ok-threads per block (17/2304 nonzero columns) compute values.
//   Those threads compute their ~4 fj + per-row fi INLINE from the image
//   (~120 scalar loads, unique sectors ~= old resize kernel's traffic,
//   redundancy L2-absorbed) — eliminating the resize kernel, the feats
//   scratch, PDL, and the dependent-launch wait: ONE graph node total.
// Replay period is DRAM-write limited: 340 MB @ ~6.6 TB/s.
// ---------------------------------------------------------------------------
__global__ void __launch_bounds__(576, 2) affinity_kernel(
    const float* __restrict__ img, float* __restrict__ out) {
    const int q  = threadIdx.x;            // float4 index within row, 0..575
    const int bx = blockIdx.x;             // 0..143
    const int b  = blockIdx.y;             // 0..15

    const int j0  = q * 4;
    const int yj  = q / 12;                // shared by the 4 j's (4 | 48)
    const int xj0 = j0 - yj * WS;
    const int xi  = bx - (bx / WS) * WS;   // constant across all 16 rows

    const int dy0 = bx / WS - yj;          // row 0's dy; +3 per row
    const float4 zero = make_float4(0.f, 0.f, 0.f, 0.f);
    float4* const optr = (float4*)(out + (((size_t)b * NPIX + bx) * NPIX)) + q;
    const size_t ostride = (size_t)144 * (NPIX / 4);   // float4s per 144 rows

    // dx mask + spatial term (image-independent).
    float sdx[4];
    bool  ok[4];
    bool  anyok = false;
#pragma unroll
    for (int k = 0; k < 4; ++k) {
        const int dx = xi - (xj0 + k);
        ok[k] = ((unsigned)(dx + RADIUS) <= 2u * RADIUS);
        anyok |= ok[k];
        sdx[k] = (float)(dx * dx);
    }

    // ---- Phase 1: out-of-band-dy zero stores (pure dy predicate).
#pragma unroll
    for (int it = 0; it < 16; ++it) {
        const int dy = dy0 + 3 * it;
        if ((unsigned)(dy + RADIUS) > 2u * RADIUS)
            __stcs(optr + it * ostride, zero);
    }

    // ---- fj invariants: only the ~5 ok-threads/block compute them.
    float fjx[4], fjy[4], fjz[4], CK[4];
    if (anyok) {
#pragma unroll
        for (int k = 0; k < 4; ++k) {
            if (ok[k]) {
                const float4 fj = feat(img, b, j0 + k);
                fjx[k] = C_DOT * fj.x;
                fjy[k] = C_DOT * fj.y;
                fjz[k] = C_DOT * fj.z;
                CK[k]  = -C_SQ * fj.w - C_SP * sdx[k];
            }
        }
    }

    // ---- Phase 2: in-band rows; store is warp-uniform, values lane-gated.
#pragma unroll
    for (int it = 0; it < 16; ++it) {
        const int dy = dy0 + 3 * it;
        if ((unsigned)(dy + RADIUS) <= 2u * RADIUS) {
            float4 v = zero;
            if (anyok) {
                const float4 fi = feat(img, b, bx + it * 144);
                const float  DI = -C_SQ * fi.w - C_SP * (float)(dy * dy);
                float* vv = (float*)&v;
#pragma unroll
                for (int k = 0; k < 4; ++k) {
                    if (ok[k]) {
                        float t = fmaf(fjx[k], fi.x, CK[k]);
                        t = fmaf(fjy[k], fi.y, t);
                        t = fmaf(fjz[k], fi.z, t);
                        vv[k] = ex2(t + DI);
                    }
                }
            }
            __stcs(optr + it * ostride, v);
        }
    }
}

// ---------------------------------------------------------------------------
extern "C" void kernel_launch(void* const* d_in, const int* in_sizes, int n_in,
                              void* d_out, int out_size) {
    const float* img = (const float*)d_in[0];
    float* out = (float*)d_out;

    dim3 grid(144, NB);                    // 2304 blocks, 16 rows each
    affinity_kernel<<<grid, 576>>>(img, out);
}